// round 15
// baseline (speedup 1.0000x reference)
#include <cuda_runtime.h>
#include <cuda_fp16.h>
#include <math.h>
#include <stdint.h>

#define BB 4
#define SS 4096
#define DIN 1024
#define DOUT 64
#define NROWS (BB*SS)          // 16384

#define NQT (SS/128)           // 32 query tiles of 128 rows per batch
#define CHUNK 512              // keys per split-KV chunk
#define MAXCH 8
#define NPART (BB*NQT*MAXCH)   // 1024

#define KST 72                 // tile row stride (f16 elems)
#define PLANE_ELEMS (64*KST)   // 4608 per plane
#define TILE2_BYTES (2*PLANE_ELEMS*2)   // 18432 B per tile (K + Vt)

// Scratch (no allocation allowed in kernel_launch)
__device__ float g_q[NROWS*DOUT];
__device__ float g_k[NROWS*DOUT];
__device__ float g_v[NROWS*DOUT];
__device__ float g_pacc[(size_t)NPART*128*DOUT];
__device__ float g_pl[NPART*128];
// Pre-split weights (fp16): [mat][n][k], k-contiguous (row = mat*64+n)
__device__ __half g_wt[3*64*1024];
// Pre-converted KV tiles (fp16): [b*64+kt][plane][4608]
__device__ __half g_tiles[(size_t)BB*64*2*PLANE_ELEMS];

// ---------------------------------------------------------------------------
// fp16 helpers: cvtf2 packs first arg into LOW 16 bits (even element)
// ---------------------------------------------------------------------------
__device__ __forceinline__ uint32_t cvtf2(float lo, float hi) {
    uint32_t r;
    asm("cvt.rn.f16x2.f32 %0, %1, %2;" : "=r"(r) : "f"(hi), "f"(lo));
    return r;
}

__device__ __forceinline__ uint32_t smem_u32(const void* p) {
    uint32_t a;
    asm("{ .reg .u64 t; cvta.to.shared.u64 t, %1; cvt.u32.u64 %0, t; }"
        : "=r"(a) : "l"(p));
    return a;
}

// mma.sync m16n8k16 row.col f16 -> f32 (frag layout validated r5-14)
__device__ __forceinline__ void mma_f16(float* d, uint32_t a0, uint32_t a1,
                                        uint32_t a2, uint32_t a3,
                                        uint32_t b0, uint32_t b1) {
    asm("mma.sync.aligned.m16n8k16.row.col.f32.f16.f16.f32 "
        "{%0,%1,%2,%3}, {%4,%5,%6,%7}, {%8,%9}, {%0,%1,%2,%3};"
        : "+f"(d[0]), "+f"(d[1]), "+f"(d[2]), "+f"(d[3])
        : "r"(a0), "r"(a1), "r"(a2), "r"(a3), "r"(b0), "r"(b1));
}

// ldmatrix m8n8.x4 (validated r9-r14)
__device__ __forceinline__ void ldm_x4(uint32_t& r0, uint32_t& r1,
                                       uint32_t& r2, uint32_t& r3, uint32_t addr) {
    asm volatile("ldmatrix.sync.aligned.m8n8.x4.shared.b16 {%0,%1,%2,%3}, [%4];"
                 : "=r"(r0), "=r"(r1), "=r"(r2), "=r"(r3) : "r"(addr));
}

// ---------------------------------------------------------------------------
// Kernel 0: convert W to fp16, transposed to [mat][n][k] (k-contiguous)
// ---------------------------------------------------------------------------
__global__ __launch_bounds__(256) void prep_w_kernel(
    const float* __restrict__ Wq, const float* __restrict__ Wk,
    const float* __restrict__ Wv)
{
    int idx = blockIdx.x * 256 + threadIdx.x;     // 0 .. 196607
    int mat = idx >> 16;
    int r   = idx & 65535;
    const float* W = (mat == 0) ? Wq : (mat == 1) ? Wk : Wv;
    float w = W[r];                                // coalesced read: r = k*64+n
    int k = r >> 6;
    int n = r & 63;
    g_wt[(mat << 16) + n * 1024 + k] = __float2half(w);
}

// ---------------------------------------------------------------------------
// Kernel 1: QKV v3 — one block does 64 rows x ALL 3 matrices.
// Per K-chunk (64): x staged coalesced (float4) with fp32->fp16 convert into
// smem; W staged via cp.async. A and B fragments both via ldmatrix.
// x read from DRAM exactly once (64MB total). grid = 256, 128 threads.
// ---------------------------------------------------------------------------
#define XST 72   // smem row stride (halves) for both x and W tiles

__global__ __launch_bounds__(128) void qkv_mma_kernel(
    const float* __restrict__ x,
    const float* __restrict__ bq, const float* __restrict__ bk,
    const float* __restrict__ bv)
{
    __shared__ __align__(16) __half xs[64 * XST];    //  9216 B
    __shared__ __align__(16) __half ws[192 * XST];   // 27648 B

    int tid  = threadIdx.x;
    int wid  = tid >> 5;      // 0..3
    int lane = tid & 31;
    int g    = lane >> 2;     // 0..7
    int t    = lane & 3;      // 0..3
    int r0   = blockIdx.x * 64;
    int rA   = r0 + wid * 16 + g;          // rows rA and rA+8

    uint32_t xs_base = smem_u32(xs);
    uint32_t ws_base = smem_u32(ws);
    // A-fragment ldmatrix lane mapping: matrices [r0-7,k0-7],[r8-15,k0-7],
    // [r0-7,k8-15],[r8-15,k8-15] -> regs a0,a1,a2,a3
    uint32_t laneoff_A = ((((lane & 7) + ((lane >> 3) & 1) * 8) + wid * 16) * XST
                          + ((lane >> 4) & 1) * 8) * 2;
    // B-fragment lane mapping (validated in attn r9+)
    uint32_t laneoff_B = ((((lane >> 4) * 8 + (lane & 7)) * XST)
                          + (((lane >> 3) & 1) * 8)) * 2;

    float acc[3][8][4];
#pragma unroll
    for (int m = 0; m < 3; m++)
#pragma unroll
        for (int nt = 0; nt < 8; nt++)
#pragma unroll
            for (int i = 0; i < 4; i++) acc[m][nt][i] = 0.f;

    for (int c0 = 0; c0 < DIN; c0 += 64) {
        // ---- stage x tile [64 rows][64 cols] fp32 -> fp16 smem (coalesced)
#pragma unroll
        for (int p = 0; p < 8; p++) {
            int idx = tid + p * 128;         // 0..1023 float4s
            int row = idx >> 4;
            int c4  = idx & 15;
            float4 v = *(const float4*)&x[(size_t)(r0 + row) * DIN + c0 + c4 * 4];
            uint32_t h0 = cvtf2(v.x, v.y);
            uint32_t h1 = cvtf2(v.z, v.w);
            *(uint2*)&xs[row * XST + c4 * 4] = make_uint2(h0, h1);
        }
        // ---- stage W tile [192 rows][64 halves] via cp.async
#pragma unroll
        for (int p = 0; p < 12; p++) {
            int idx = tid + p * 128;         // 0..1535 16B chunks
            int row = idx >> 3;              // 0..191 (= mat*64 + n)
            int c8  = idx & 7;
            asm volatile("cp.async.cg.shared.global [%0], [%1], 16;"
                         :: "r"(ws_base + (row * XST + c8 * 8) * 2),
                            "l"((const char*)&g_wt[(size_t)row * 1024 + c0 + c8 * 8])
                         : "memory");
        }
        asm volatile("cp.async.commit_group;" ::: "memory");
        asm volatile("cp.async.wait_group 0;" ::: "memory");
        __syncthreads();

        // ---- compute: 4 k-steps x 3 mats x 4 n-pairs
#pragma unroll
        for (int ks = 0; ks < 4; ks++) {
            uint32_t a0, a1, a2, a3;
            ldm_x4(a0, a1, a2, a3, xs_base + (ks * 16) * 2 + laneoff_A);
#pragma unroll
            for (int m = 0; m < 3; m++) {
#pragma unroll
                for (int np = 0; np < 4; np++) {
                    uint32_t off = ((m * 64 + np * 16) * XST + ks * 16) * 2;
                    uint32_t b0a, b1a, b0b, b1b;
                    ldm_x4(b0a, b1a, b0b, b1b, ws_base + off + laneoff_B);
                    mma_f16(acc[m][2*np],   a0, a1, a2, a3, b0a, b1a);
                    mma_f16(acc[m][2*np+1], a0, a1, a2, a3, b0b, b1b);
                }
            }
        }
        __syncthreads();   // tile reads done before next staging overwrites
    }

#pragma unroll
    for (int m = 0; m < 3; m++) {
        float* out = (m == 0) ? g_q : (m == 1) ? g_k : g_v;
        const float* bias = (m == 0) ? bq : (m == 1) ? bk : bv;
#pragma unroll
        for (int nt = 0; nt < 8; nt++) {
            int col = nt * 8 + 2 * t;
            float b0 = bias[col], b1 = bias[col + 1];
            float2 o0 = make_float2(acc[m][nt][0] + b0, acc[m][nt][1] + b1);
            float2 o1 = make_float2(acc[m][nt][2] + b0, acc[m][nt][3] + b1);
            *(float2*)&out[(size_t)rA * DOUT + col] = o0;
            *(float2*)&out[(size_t)(rA + 8) * DOUT + col] = o1;
        }
    }
}

// ---------------------------------------------------------------------------
// Kernel 1b: pre-convert K/V into fp16 tile images (UNCHANGED)
// ---------------------------------------------------------------------------
__global__ __launch_bounds__(256) void preconv_kernel()
{
    __shared__ float vsm[64 * 65];

    int bt  = blockIdx.x;             // b*64 + kt
    int b   = bt >> 6;
    int kt  = bt & 63;
    int tid = threadIdx.x;

    __half* tk = &g_tiles[(size_t)bt * 2 * PLANE_ELEMS];
    __half* tv = tk + PLANE_ELEMS;

#pragma unroll
    for (int p = 0; p < 4; p++) {
        int idx4 = tid + p * 256;            // 0..1023 float4s
        int key  = idx4 >> 4;
        int dq   = (idx4 & 15) * 4;
        size_t gsrc = ((size_t)b * SS + kt * 64 + key) * DOUT + dq;

        float4 kv = *(const float4*)&g_k[gsrc];
        uint32_t h0 = cvtf2(kv.x, kv.y), h1 = cvtf2(kv.z, kv.w);
        *(uint2*)&tk[key * KST + dq] = make_uint2(h0, h1);

        float4 vv = *(const float4*)&g_v[gsrc];
        vsm[key * 65 + dq + 0] = vv.x;
        vsm[key * 65 + dq + 1] = vv.y;
        vsm[key * 65 + dq + 2] = vv.z;
        vsm[key * 65 + dq + 3] = vv.w;
    }
    __syncthreads();

    {
        int d  = tid >> 2;
        int kq = (tid & 3) * 16;
        uint32_t h[8];
#pragma unroll
        for (int i = 0; i < 8; i++) {
            h[i] = cvtf2(vsm[(kq + 2 * i) * 65 + d],
                         vsm[(kq + 2 * i + 1) * 65 + d]);
        }
        uint4* dst = (uint4*)&tv[d * KST + kq];
        dst[0] = make_uint4(h[0], h[1], h[2], h[3]);
        dst[1] = make_uint4(h[4], h[5], h[6], h[7]);
    }
}

// ---------------------------------------------------------------------------
// Kernel 2: flash-attention partial, fp16 single-pass (UNCHANGED; 38.3us)
// ---------------------------------------------------------------------------
__global__ __launch_bounds__(256, 2) void attn_mma_kernel()
{
    extern __shared__ __align__(16) char smdyn[];

    int blk = blockIdx.x;
    int b   = blk / (NQT * MAXCH);
    int rem = blk % (NQT * MAXCH);
    int qt  = rem / MAXCH;
    int ch  = rem % MAXCH;
    int nch = (qt >> 2) + 1;   // ceil((qt+1)*128 / 512)
    if (ch >= nch) return;

    int tid  = threadIdx.x;
    int w    = tid >> 5;
    int lane = tid & 31;
    int g    = lane >> 2;
    int t    = lane & 3;

    int rg  = qt * 128 + w * 16 + g;   // query rows rg and rg+8
    int rg8 = rg + 8;
    int rwmin = qt * 128 + w * 16;     // min row in this warp's tile

    uint32_t smT_base = smem_u32(smdyn);
    uint32_t laneoff = ((((lane >> 4) * 8 + (lane & 7)) * KST
                         + ((lane >> 3) & 1) * 8) * 2);

    const float SCALE = 0.015625f;   // 1/sqrt(4096)
    uint32_t qh[4][4];
    {
        const float* q0 = &g_q[((size_t)b * SS + rg) * DOUT];
        const float* q8 = &g_q[((size_t)b * SS + rg8) * DOUT];
#pragma unroll
        for (int ks = 0; ks < 4; ks++) {
            float2 xa = *(const float2*)&q0[ks * 16 + 2 * t];
            float2 xc = *(const float2*)&q8[ks * 16 + 2 * t];
            float2 xb = *(const float2*)&q0[ks * 16 + 2 * t + 8];
            float2 xd = *(const float2*)&q8[ks * 16 + 2 * t + 8];
            qh[ks][0] = cvtf2(xa.x * SCALE, xa.y * SCALE);
            qh[ks][1] = cvtf2(xc.x * SCALE, xc.y * SCALE);
            qh[ks][2] = cvtf2(xb.x * SCALE, xb.y * SCALE);
            qh[ks][3] = cvtf2(xd.x * SCALE, xd.y * SCALE);
        }
    }

    float o[8][4];
#pragma unroll
    for (int nd = 0; nd < 8; nd++)
#pragma unroll
        for (int i = 0; i < 4; i++) o[nd][i] = 0.f;
    float lg = 0.f, lg8 = 0.f;

    int k0 = ch * CHUNK;
    int k1 = min(k0 + CHUNK, (qt + 1) * 128);

    {
        const char* src =
            (const char*)&g_tiles[(size_t)(b * 64 + (k0 >> 6)) * 2 * PLANE_ELEMS];
        for (int i = tid; i < 1152; i += 256) {
            asm volatile("cp.async.cg.shared.global [%0], [%1], 16;"
                         :: "r"(smT_base + i * 16), "l"(src + (size_t)i * 16)
                         : "memory");
        }
        asm volatile("cp.async.commit_group;" ::: "memory");
    }

    int ib = 0;
    for (int kt = k0; kt < k1; kt += 64, ib ^= 1) {
        int ktn = kt + 64;
        if (ktn < k1) {
            uint32_t nb = smT_base + (ib ^ 1) * TILE2_BYTES;
            const char* src =
                (const char*)&g_tiles[(size_t)(b * 64 + (ktn >> 6)) * 2 * PLANE_ELEMS];
            for (int i = tid; i < 1152; i += 256) {
                asm volatile("cp.async.cg.shared.global [%0], [%1], 16;"
                             :: "r"(nb + i * 16), "l"(src + (size_t)i * 16)
                             : "memory");
            }
            asm volatile("cp.async.commit_group;" ::: "memory");
            asm volatile("cp.async.wait_group 1;" ::: "memory");
        } else {
            asm volatile("cp.async.wait_group 0;" ::: "memory");
        }
        __syncthreads();

        uint32_t bufb = smT_base + ib * TILE2_BYTES;
        uint32_t aK = bufb + laneoff;
        uint32_t aV = bufb + PLANE_ELEMS * 2 + laneoff;

        float c[8][4];
#pragma unroll
        for (int nc = 0; nc < 8; nc++)
#pragma unroll
            for (int i = 0; i < 4; i++) c[nc][i] = 0.f;

#pragma unroll
        for (int ks = 0; ks < 4; ks++) {
#pragma unroll
            for (int np = 0; np < 4; np++) {
                uint32_t off = (np * 16 * KST + ks * 16) * 2;
                uint32_t b0a, b1a, b0b, b1b;
                ldm_x4(b0a, b1a, b0b, b1b, aK + off);
                mma_f16(c[2*np],   qh[ks][0], qh[ks][1], qh[ks][2], qh[ks][3], b0a, b1a);
                mma_f16(c[2*np+1], qh[ks][0], qh[ks][1], qh[ks][2], qh[ks][3], b0b, b1b);
            }
        }

        uint32_t pah[4][4];
        if (kt + 63 <= rwmin) {
#pragma unroll
            for (int nc = 0; nc < 8; nc++) {
                float e0 = __expf(c[nc][0]);
                float e1 = __expf(c[nc][1]);
                float e2 = __expf(c[nc][2]);
                float e3 = __expf(c[nc][3]);
                lg  += e0 + e1;
                lg8 += e2 + e3;
                uint32_t h01 = cvtf2(e0, e1), h23 = cvtf2(e2, e3);
                int j = nc >> 1;
                if ((nc & 1) == 0) { pah[j][0] = h01; pah[j][1] = h23; }
                else               { pah[j][2] = h01; pah[j][3] = h23; }
            }
        } else {
#pragma unroll
            for (int nc = 0; nc < 8; nc++) {
                int col0 = kt + nc * 8 + 2 * t;
                int col1 = col0 + 1;
                float e0 = (col0 <= rg)  ? __expf(c[nc][0]) : 0.f;
                float e1 = (col1 <= rg)  ? __expf(c[nc][1]) : 0.f;
                float e2 = (col0 <= rg8) ? __expf(c[nc][2]) : 0.f;
                float e3 = (col1 <= rg8) ? __expf(c[nc][3]) : 0.f;
                lg  += e0 + e1;
                lg8 += e2 + e3;
                uint32_t h01 = cvtf2(e0, e1), h23 = cvtf2(e2, e3);
                int j = nc >> 1;
                if ((nc & 1) == 0) { pah[j][0] = h01; pah[j][1] = h23; }
                else               { pah[j][2] = h01; pah[j][3] = h23; }
            }
        }

#pragma unroll
        for (int j = 0; j < 4; j++) {
#pragma unroll
            for (int np = 0; np < 4; np++) {
                uint32_t off = (np * 16 * KST + j * 16) * 2;
                uint32_t b0a, b1a, b0b, b1b;
                ldm_x4(b0a, b1a, b0b, b1b, aV + off);
                mma_f16(o[2*np],   pah[j][0], pah[j][1], pah[j][2], pah[j][3], b0a, b1a);
                mma_f16(o[2*np+1], pah[j][0], pah[j][1], pah[j][2], pah[j][3], b0b, b1b);
            }
        }
        __syncthreads();
    }

    lg  += __shfl_xor_sync(0xffffffffu, lg, 1);
    lg  += __shfl_xor_sync(0xffffffffu, lg, 2);
    lg8 += __shfl_xor_sync(0xffffffffu, lg8, 1);
    lg8 += __shfl_xor_sync(0xffffffffu, lg8, 2);

    int pidx = (b * NQT + qt) * MAXCH + ch;
    int rl = w * 16 + g;
    if (t == 0) {
        g_pl[pidx * 128 + rl]     = lg;
        g_pl[pidx * 128 + rl + 8] = lg8;
    }
    float* pa0 = &g_pacc[((size_t)pidx * 128 + rl) * DOUT];
    float* pa8 = &g_pacc[((size_t)pidx * 128 + rl + 8) * DOUT];
#pragma unroll
    for (int nd = 0; nd < 8; nd++) {
        *(float2*)&pa0[nd * 8 + 2 * t] = make_float2(o[nd][0], o[nd][1]);
        *(float2*)&pa8[nd * 8 + 2 * t] = make_float2(o[nd][2], o[nd][3]);
    }
}

// ---------------------------------------------------------------------------
// Kernel 3: combine split-KV partials. 256 threads = 4 rows x 64 dims.
// ---------------------------------------------------------------------------
__global__ __launch_bounds__(256) void combine_kernel(float* __restrict__ out)
{
    int rowg = blockIdx.x * 4 + (threadIdx.x >> 6);
    int b    = rowg / SS;
    int row  = rowg % SS;
    int qt   = row >> 7;
    int r    = row & 127;
    int nch  = (qt >> 2) + 1;
    int d    = threadIdx.x & 63;
    int pbase = (b * NQT + qt) * MAXCH;

    float L = 0.f, o = 0.f;
    for (int c = 0; c < nch; c++) {
        L += g_pl[(pbase + c) * 128 + r];
        o += g_pacc[((size_t)(pbase + c) * 128 + r) * DOUT + d];
    }
    out[((size_t)b * SS + row) * DOUT + d] = o / L;
}

// ---------------------------------------------------------------------------
extern "C" void kernel_launch(void* const* d_in, const int* in_sizes, int n_in,
                              void* d_out, int out_size)
{
    const float* x  = (const float*)d_in[0];
    const float* Wq = (const float*)d_in[1];
    const float* bq = (const float*)d_in[2];
    const float* Wk = (const float*)d_in[3];
    const float* bk = (const float*)d_in[4];
    const float* Wv = (const float*)d_in[5];
    const float* bv = (const float*)d_in[6];
    float* out = (float*)d_out;

    cudaFuncSetAttribute(attn_mma_kernel,
                         cudaFuncAttributeMaxDynamicSharedMemorySize,
                         2 * TILE2_BYTES);

    prep_w_kernel<<<768, 256>>>(Wq, Wk, Wv);
    qkv_mma_kernel<<<NROWS / 64, 128>>>(x, bq, bk, bv);
    preconv_kernel<<<BB * 64, 256>>>();
    attn_mma_kernel<<<NPART, 256, 2 * TILE2_BYTES>>>();
    combine_kernel<<<BB * SS / 4, 256>>>(out);
}

// round 16
// speedup vs baseline: 1.0883x; 1.0883x over previous
#include <cuda_runtime.h>
#include <cuda_fp16.h>
#include <math.h>
#include <stdint.h>

#define BB 4
#define SS 4096
#define DIN 1024
#define DOUT 64
#define NROWS (BB*SS)          // 16384

#define NQT (SS/128)           // 32 query tiles of 128 rows per batch
#define CHUNK 512              // keys per split-KV chunk
#define MAXCH 8
#define NPART (BB*NQT*MAXCH)   // 1024

#define KST 72                 // tile row stride (f16 elems)
#define PLANE_ELEMS (64*KST)   // 4608 per plane
#define TILE2_BYTES (2*PLANE_ELEMS*2)   // 18432 B per tile (K + Vt)

// Scratch (no allocation allowed in kernel_launch)
__device__ float g_q[NROWS*DOUT];
__device__ float g_pacc[(size_t)NPART*128*DOUT];
__device__ float g_pl[NPART*128];
// Pre-split weights (fp16): [mat][n][k], k-contiguous
__device__ __half g_wt[3*64*1024];
// Pre-converted KV tiles (fp16): [global_row/64][plane][4608]
//   plane 0 = K [key][d], 1 = Vt [d][key]   (written directly by qkv epilogue)
__device__ __half g_tiles[(size_t)BB*64*2*PLANE_ELEMS];

// ---------------------------------------------------------------------------
// fp16 helpers: cvtf2 packs first arg into LOW 16 bits (even element)
// ---------------------------------------------------------------------------
__device__ __forceinline__ uint32_t cvtf2(float lo, float hi) {
    uint32_t r;
    asm("cvt.rn.f16x2.f32 %0, %1, %2;" : "=r"(r) : "f"(hi), "f"(lo));
    return r;
}

__device__ __forceinline__ uint32_t smem_u32(const void* p) {
    uint32_t a;
    asm("{ .reg .u64 t; cvta.to.shared.u64 t, %1; cvt.u32.u64 %0, t; }"
        : "=r"(a) : "l"(p));
    return a;
}

// mma.sync m16n8k16 row.col f16 -> f32 (frag layout validated r5-15)
__device__ __forceinline__ void mma_f16(float* d, uint32_t a0, uint32_t a1,
                                        uint32_t a2, uint32_t a3,
                                        uint32_t b0, uint32_t b1) {
    asm("mma.sync.aligned.m16n8k16.row.col.f32.f16.f16.f32 "
        "{%0,%1,%2,%3}, {%4,%5,%6,%7}, {%8,%9}, {%0,%1,%2,%3};"
        : "+f"(d[0]), "+f"(d[1]), "+f"(d[2]), "+f"(d[3])
        : "r"(a0), "r"(a1), "r"(a2), "r"(a3), "r"(b0), "r"(b1));
}

// ldmatrix m8n8.x4 (validated r9-r15)
__device__ __forceinline__ void ldm_x4(uint32_t& r0, uint32_t& r1,
                                       uint32_t& r2, uint32_t& r3, uint32_t addr) {
    asm volatile("ldmatrix.sync.aligned.m8n8.x4.shared.b16 {%0,%1,%2,%3}, [%4];"
                 : "=r"(r0), "=r"(r1), "=r"(r2), "=r"(r3) : "r"(addr));
}

// ---------------------------------------------------------------------------
// Kernel 0: convert W to fp16, transposed to [mat][n][k] (k-contiguous)
// ---------------------------------------------------------------------------
__global__ __launch_bounds__(256) void prep_w_kernel(
    const float* __restrict__ Wq, const float* __restrict__ Wk,
    const float* __restrict__ Wv)
{
    int idx = blockIdx.x * 256 + threadIdx.x;     // 0 .. 196607
    int mat = idx >> 16;
    int r   = idx & 65535;
    const float* W = (mat == 0) ? Wq : (mat == 1) ? Wk : Wv;
    float w = W[r];                                // coalesced read: r = k*64+n
    int k = r >> 6;
    int n = r & 63;
    g_wt[(mat << 16) + n * 1024 + k] = __float2half(w);
}

// ---------------------------------------------------------------------------
// Kernel 1: QKV (r14 mainloop verbatim) + fused tile epilogue.
// grid (3, 256): mat = blockIdx.x. Block covers global rows
// blockIdx.y*64..+63 == attention tile bt = blockIdx.y.
//   mat 0 -> g_q fp32 (attn Q-frag source)
//   mat 1 -> K plane of g_tiles[bt]  (fp16, [key][d], +bias)
//   mat 2 -> Vt plane of g_tiles[bt] (fp16, [d][key], +bias, via smem transpose)
// g_k/g_v fp32 and the preconv kernel are eliminated.
// ---------------------------------------------------------------------------
#define QWTS 40   // f16 elements per smem B row (80B stride)
#define QBUF (64*QWTS)   // 2560 halves = 5120 B per buffer

__global__ __launch_bounds__(128) void qkv_mma_kernel(
    const float* __restrict__ x,
    const float* __restrict__ bq, const float* __restrict__ bk,
    const float* __restrict__ bv)
{
    __shared__ __align__(16) __half bs[2 * QBUF];   // 10240 B
    __shared__ __align__(16) __half vsm[64 * KST];  //  9216 B (V transpose stage)

    int tid  = threadIdx.x;
    int wid  = tid >> 5;
    int lane = tid & 31;
    int g    = lane >> 2;     // 0..7
    int t    = lane & 3;      // 0..3
    int mat  = blockIdx.x;
    int bt   = blockIdx.y;                 // attention tile index
    int r0   = bt * 64;
    int lrow = wid * 16 + g;               // local rows lrow and lrow+8
    int rA   = r0 + lrow;

    const __half* wsrc = &g_wt[mat << 16];
    const float* bias = (mat == 0) ? bq : (mat == 1) ? bk : bv;

    uint32_t bbase = smem_u32(bs);
    uint32_t laneoff = (((lane >> 4) * 8 + (lane & 7)) * QWTS) * 2
                       + (((lane >> 3) & 1) * 8) * 2;

    float acc[8][4];
#pragma unroll
    for (int nt = 0; nt < 8; nt++)
#pragma unroll
        for (int i = 0; i < 4; i++) acc[nt][i] = 0.f;

    const float* xlo = &x[(size_t)rA * DIN];
    const float* xhi = &x[(size_t)(rA + 8) * DIN];

    // prologue: stage chunk 0 into buffer 0 (256 uint4 = 4096B of W data)
#pragma unroll
    for (int i = tid; i < 256; i += 128) {
        int row = i >> 2;
        int cc  = i & 3;
        asm volatile("cp.async.cg.shared.global [%0], [%1], 16;"
                     :: "r"(bbase + (row * QWTS + cc * 8) * 2),
                        "l"((const char*)&wsrc[row * 1024 + cc * 8])
                     : "memory");
    }
    asm volatile("cp.async.commit_group;" ::: "memory");

    int ib = 0;
    for (int c = 0; c < 32; c++, ib ^= 1) {
        if (c + 1 < 32) {
            int c0n = (c + 1) * 32;
            uint32_t nb = bbase + (ib ^ 1) * QBUF * 2;
#pragma unroll
            for (int i = tid; i < 256; i += 128) {
                int row = i >> 2;
                int cc  = i & 3;
                asm volatile("cp.async.cg.shared.global [%0], [%1], 16;"
                             :: "r"(nb + (row * QWTS + cc * 8) * 2),
                                "l"((const char*)&wsrc[row * 1024 + c0n + cc * 8])
                             : "memory");
            }
            asm volatile("cp.async.commit_group;" ::: "memory");
            asm volatile("cp.async.wait_group 1;" ::: "memory");
        } else {
            asm volatile("cp.async.wait_group 0;" ::: "memory");
        }
        __syncthreads();

        uint32_t bufb = bbase + ib * QBUF * 2;
        int c0 = c * 32;
#pragma unroll
        for (int ks = 0; ks < 2; ks++) {
            int kk = c0 + ks * 16;
            float2 xa = *(const float2*)&xlo[kk + 2 * t];
            float2 xb = *(const float2*)&xlo[kk + 2 * t + 8];
            float2 xc = *(const float2*)&xhi[kk + 2 * t];
            float2 xd = *(const float2*)&xhi[kk + 2 * t + 8];
            uint32_t a0 = cvtf2(xa.x, xa.y);
            uint32_t a1 = cvtf2(xc.x, xc.y);
            uint32_t a2 = cvtf2(xb.x, xb.y);
            uint32_t a3 = cvtf2(xd.x, xd.y);

#pragma unroll
            for (int np = 0; np < 4; np++) {     // nt pair 2np, 2np+1
                uint32_t off = (np * 16 * QWTS + ks * 16) * 2;
                uint32_t b0a, b1a, b0b, b1b;
                ldm_x4(b0a, b1a, b0b, b1b, bufb + off + laneoff);
                mma_f16(acc[2*np],   a0, a1, a2, a3, b0a, b1a);
                mma_f16(acc[2*np+1], a0, a1, a2, a3, b0b, b1b);
            }
        }
        __syncthreads();
    }

    // ---- epilogue ----
    if (mat == 0) {
        // Q: fp32 + bias to g_q (attn reads this)
#pragma unroll
        for (int nt = 0; nt < 8; nt++) {
            int col = nt * 8 + 2 * t;
            float b0 = bias[col], b1 = bias[col + 1];
            float2 o0 = make_float2(acc[nt][0] + b0, acc[nt][1] + b1);
            float2 o1 = make_float2(acc[nt][2] + b0, acc[nt][3] + b1);
            *(float2*)&g_q[(size_t)rA * DOUT + col] = o0;
            *(float2*)&g_q[(size_t)(rA + 8) * DOUT + col] = o1;
        }
    } else if (mat == 1) {
        // K: fp16 + bias directly into K plane of g_tiles[bt]  ([key][d])
        __half* tk = &g_tiles[(size_t)bt * 2 * PLANE_ELEMS];
#pragma unroll
        for (int nt = 0; nt < 8; nt++) {
            int col = nt * 8 + 2 * t;
            float b0 = bias[col], b1 = bias[col + 1];
            uint32_t h0 = cvtf2(acc[nt][0] + b0, acc[nt][1] + b1);
            uint32_t h1 = cvtf2(acc[nt][2] + b0, acc[nt][3] + b1);
            *(uint32_t*)&tk[lrow * KST + col]       = h0;
            *(uint32_t*)&tk[(lrow + 8) * KST + col] = h1;
        }
    } else {
        // V: fp16 + bias into smem [key][d], then transposed write to Vt plane
#pragma unroll
        for (int nt = 0; nt < 8; nt++) {
            int col = nt * 8 + 2 * t;
            float b0 = bias[col], b1 = bias[col + 1];
            uint32_t h0 = cvtf2(acc[nt][0] + b0, acc[nt][1] + b1);
            uint32_t h1 = cvtf2(acc[nt][2] + b0, acc[nt][3] + b1);
            *(uint32_t*)&vsm[lrow * KST + col]       = h0;
            *(uint32_t*)&vsm[(lrow + 8) * KST + col] = h1;
        }
        __syncthreads();
        // transposed write: thread -> d = tid>>1, keys kh*32..kh*32+31
        __half* tv = &g_tiles[(size_t)bt * 2 * PLANE_ELEMS + PLANE_ELEMS];
        int d  = tid >> 1;
        int kh = tid & 1;
        uint32_t hp[16];
#pragma unroll
        for (int i = 0; i < 16; i++) {
            int key = kh * 32 + 2 * i;
            __half f0 = vsm[key * KST + d];
            __half f1 = vsm[(key + 1) * KST + d];
            uint32_t u0 = (uint32_t)__half_as_ushort(f0);
            uint32_t u1 = (uint32_t)__half_as_ushort(f1);
            hp[i] = u0 | (u1 << 16);
        }
        uint4* dst = (uint4*)&tv[d * KST + kh * 32];
#pragma unroll
        for (int i = 0; i < 4; i++)
            dst[i] = make_uint4(hp[4*i], hp[4*i+1], hp[4*i+2], hp[4*i+3]);
    }
}

// ---------------------------------------------------------------------------
// Kernel 2: flash-attention partial, fp16 single-pass (UNCHANGED; 38.3us)
// ---------------------------------------------------------------------------
__global__ __launch_bounds__(256, 2) void attn_mma_kernel()
{
    extern __shared__ __align__(16) char smdyn[];

    int blk = blockIdx.x;
    int b   = blk / (NQT * MAXCH);
    int rem = blk % (NQT * MAXCH);
    int qt  = rem / MAXCH;
    int ch  = rem % MAXCH;
    int nch = (qt >> 2) + 1;   // ceil((qt+1)*128 / 512)
    if (ch >= nch) return;

    int tid  = threadIdx.x;
    int w    = tid >> 5;
    int lane = tid & 31;
    int g    = lane >> 2;
    int t    = lane & 3;

    int rg  = qt * 128 + w * 16 + g;   // query rows rg and rg+8
    int rg8 = rg + 8;
    int rwmin = qt * 128 + w * 16;     // min row in this warp's tile

    uint32_t smT_base = smem_u32(smdyn);
    uint32_t laneoff = ((((lane >> 4) * 8 + (lane & 7)) * KST
                         + ((lane >> 3) & 1) * 8) * 2);

    const float SCALE = 0.015625f;   // 1/sqrt(4096)
    uint32_t qh[4][4];
    {
        const float* q0 = &g_q[((size_t)b * SS + rg) * DOUT];
        const float* q8 = &g_q[((size_t)b * SS + rg8) * DOUT];
#pragma unroll
        for (int ks = 0; ks < 4; ks++) {
            float2 xa = *(const float2*)&q0[ks * 16 + 2 * t];
            float2 xc = *(const float2*)&q8[ks * 16 + 2 * t];
            float2 xb = *(const float2*)&q0[ks * 16 + 2 * t + 8];
            float2 xd = *(const float2*)&q8[ks * 16 + 2 * t + 8];
            qh[ks][0] = cvtf2(xa.x * SCALE, xa.y * SCALE);
            qh[ks][1] = cvtf2(xc.x * SCALE, xc.y * SCALE);
            qh[ks][2] = cvtf2(xb.x * SCALE, xb.y * SCALE);
            qh[ks][3] = cvtf2(xd.x * SCALE, xd.y * SCALE);
        }
    }

    float o[8][4];
#pragma unroll
    for (int nd = 0; nd < 8; nd++)
#pragma unroll
        for (int i = 0; i < 4; i++) o[nd][i] = 0.f;
    float lg = 0.f, lg8 = 0.f;

    int k0 = ch * CHUNK;
    int k1 = min(k0 + CHUNK, (qt + 1) * 128);

    {
        const char* src =
            (const char*)&g_tiles[(size_t)(b * 64 + (k0 >> 6)) * 2 * PLANE_ELEMS];
        for (int i = tid; i < 1152; i += 256) {
            asm volatile("cp.async.cg.shared.global [%0], [%1], 16;"
                         :: "r"(smT_base + i * 16), "l"(src + (size_t)i * 16)
                         : "memory");
        }
        asm volatile("cp.async.commit_group;" ::: "memory");
    }

    int ib = 0;
    for (int kt = k0; kt < k1; kt += 64, ib ^= 1) {
        int ktn = kt + 64;
        if (ktn < k1) {
            uint32_t nb = smT_base + (ib ^ 1) * TILE2_BYTES;
            const char* src =
                (const char*)&g_tiles[(size_t)(b * 64 + (ktn >> 6)) * 2 * PLANE_ELEMS];
            for (int i = tid; i < 1152; i += 256) {
                asm volatile("cp.async.cg.shared.global [%0], [%1], 16;"
                             :: "r"(nb + i * 16), "l"(src + (size_t)i * 16)
                             : "memory");
            }
            asm volatile("cp.async.commit_group;" ::: "memory");
            asm volatile("cp.async.wait_group 1;" ::: "memory");
        } else {
            asm volatile("cp.async.wait_group 0;" ::: "memory");
        }
        __syncthreads();

        uint32_t bufb = smT_base + ib * TILE2_BYTES;
        uint32_t aK = bufb + laneoff;
        uint32_t aV = bufb + PLANE_ELEMS * 2 + laneoff;

        float c[8][4];
#pragma unroll
        for (int nc = 0; nc < 8; nc++)
#pragma unroll
            for (int i = 0; i < 4; i++) c[nc][i] = 0.f;

#pragma unroll
        for (int ks = 0; ks < 4; ks++) {
#pragma unroll
            for (int np = 0; np < 4; np++) {
                uint32_t off = (np * 16 * KST + ks * 16) * 2;
                uint32_t b0a, b1a, b0b, b1b;
                ldm_x4(b0a, b1a, b0b, b1b, aK + off);
                mma_f16(c[2*np],   qh[ks][0], qh[ks][1], qh[ks][2], qh[ks][3], b0a, b1a);
                mma_f16(c[2*np+1], qh[ks][0], qh[ks][1], qh[ks][2], qh[ks][3], b0b, b1b);
            }
        }

        uint32_t pah[4][4];
        if (kt + 63 <= rwmin) {
#pragma unroll
            for (int nc = 0; nc < 8; nc++) {
                float e0 = __expf(c[nc][0]);
                float e1 = __expf(c[nc][1]);
                float e2 = __expf(c[nc][2]);
                float e3 = __expf(c[nc][3]);
                lg  += e0 + e1;
                lg8 += e2 + e3;
                uint32_t h01 = cvtf2(e0, e1), h23 = cvtf2(e2, e3);
                int j = nc >> 1;
                if ((nc & 1) == 0) { pah[j][0] = h01; pah[j][1] = h23; }
                else               { pah[j][2] = h01; pah[j][3] = h23; }
            }
        } else {
#pragma unroll
            for (int nc = 0; nc < 8; nc++) {
                int col0 = kt + nc * 8 + 2 * t;
                int col1 = col0 + 1;
                float e0 = (col0 <= rg)  ? __expf(c[nc][0]) : 0.f;
                float e1 = (col1 <= rg)  ? __expf(c[nc][1]) : 0.f;
                float e2 = (col0 <= rg8) ? __expf(c[nc][2]) : 0.f;
                float e3 = (col1 <= rg8) ? __expf(c[nc][3]) : 0.f;
                lg  += e0 + e1;
                lg8 += e2 + e3;
                uint32_t h01 = cvtf2(e0, e1), h23 = cvtf2(e2, e3);
                int j = nc >> 1;
                if ((nc & 1) == 0) { pah[j][0] = h01; pah[j][1] = h23; }
                else               { pah[j][2] = h01; pah[j][3] = h23; }
            }
        }

#pragma unroll
        for (int j = 0; j < 4; j++) {
#pragma unroll
            for (int np = 0; np < 4; np++) {
                uint32_t off = (np * 16 * KST + j * 16) * 2;
                uint32_t b0a, b1a, b0b, b1b;
                ldm_x4(b0a, b1a, b0b, b1b, aV + off);
                mma_f16(o[2*np],   pah[j][0], pah[j][1], pah[j][2], pah[j][3], b0a, b1a);
                mma_f16(o[2*np+1], pah[j][0], pah[j][1], pah[j][2], pah[j][3], b0b, b1b);
            }
        }
        __syncthreads();
    }

    lg  += __shfl_xor_sync(0xffffffffu, lg, 1);
    lg  += __shfl_xor_sync(0xffffffffu, lg, 2);
    lg8 += __shfl_xor_sync(0xffffffffu, lg8, 1);
    lg8 += __shfl_xor_sync(0xffffffffu, lg8, 2);

    int pidx = (b * NQT + qt) * MAXCH + ch;
    int rl = w * 16 + g;
    if (t == 0) {
        g_pl[pidx * 128 + rl]     = lg;
        g_pl[pidx * 128 + rl + 8] = lg8;
    }
    float* pa0 = &g_pacc[((size_t)pidx * 128 + rl) * DOUT];
    float* pa8 = &g_pacc[((size_t)pidx * 128 + rl + 8) * DOUT];
#pragma unroll
    for (int nd = 0; nd < 8; nd++) {
        *(float2*)&pa0[nd * 8 + 2 * t] = make_float2(o[nd][0], o[nd][1]);
        *(float2*)&pa8[nd * 8 + 2 * t] = make_float2(o[nd][2], o[nd][3]);
    }
}

// ---------------------------------------------------------------------------
// Kernel 3: combine split-KV partials. 256 threads = 4 rows x 64 dims.
// ---------------------------------------------------------------------------
__global__ __launch_bounds__(256) void combine_kernel(float* __restrict__ out)
{
    int rowg = blockIdx.x * 4 + (threadIdx.x >> 6);
    int b    = rowg / SS;
    int row  = rowg % SS;
    int qt   = row >> 7;
    int r    = row & 127;
    int nch  = (qt >> 2) + 1;
    int d    = threadIdx.x & 63;
    int pbase = (b * NQT + qt) * MAXCH;

    float L = 0.f, o = 0.f;
    for (int c = 0; c < nch; c++) {
        L += g_pl[(pbase + c) * 128 + r];
        o += g_pacc[((size_t)(pbase + c) * 128 + r) * DOUT + d];
    }
    out[((size_t)b * SS + row) * DOUT + d] = o / L;
}

// ---------------------------------------------------------------------------
extern "C" void kernel_launch(void* const* d_in, const int* in_sizes, int n_in,
                              void* d_out, int out_size)
{
    const float* x  = (const float*)d_in[0];
    const float* Wq = (const float*)d_in[1];
    const float* bq = (const float*)d_in[2];
    const float* Wk = (const float*)d_in[3];
    const float* bk = (const float*)d_in[4];
    const float* Wv = (const float*)d_in[5];
    const float* bv = (const float*)d_in[6];
    float* out = (float*)d_out;

    cudaFuncSetAttribute(attn_mma_kernel,
                         cudaFuncAttributeMaxDynamicSharedMemorySize,
                         2 * TILE2_BYTES);

    prep_w_kernel<<<768, 256>>>(Wq, Wk, Wv);
    dim3 gq(3, NROWS / 64);   // mat fastest-varying; block == one attn tile
    qkv_mma_kernel<<<gq, 128>>>(x, bq, bk, bv);
    attn_mma_kernel<<<NPART, 256, 2 * TILE2_BYTES>>>();
    combine_kernel<<<BB * SS / 4, 256>>>(out);
}